// round 2
// baseline (speedup 1.0000x reference)
#include <cuda_runtime.h>

#define NROWS 16384
#define KCODES 8192
#define DDIM 256

#define BM 64      // rows per block tile
#define BK 128     // codes per smem tile
#define BD 16      // D-chunk
#define KSPAN 2048 // codes per block (blockIdx.y span)

__device__ float g_c[NROWS];
__device__ unsigned long long g_best[NROWS];
__device__ double g_loss;

// ---------------------------------------------------------------------------
// Kernel 1: per-row |z|^2, init best[] and loss accumulator (re-done every
// launch -> graph-replay safe).
// ---------------------------------------------------------------------------
__global__ void k_init(const float* __restrict__ z) {
    int row  = blockIdx.x * 8 + (threadIdx.x >> 5);
    int lane = threadIdx.x & 31;
    const float4* zp = (const float4*)(z + (size_t)row * DDIM);
    float4 a = zp[lane * 2];
    float4 b = zp[lane * 2 + 1];
    float s = a.x*a.x + a.y*a.y + a.z*a.z + a.w*a.w
            + b.x*b.x + b.y*b.y + b.z*b.z + b.w*b.w;
    #pragma unroll
    for (int o = 16; o > 0; o >>= 1) s += __shfl_xor_sync(0xffffffffu, s, o);
    if (lane == 0) {
        g_c[row] = s;
        g_best[row] = ~0ULL;
    }
    if (blockIdx.x == 0 && threadIdx.x == 0) g_loss = 0.0;
}

// ---------------------------------------------------------------------------
// Kernel 2: fused distance GEMM + quantized argmin.
// t = fl(c - 2*dot) per (row, code); argmin with first-index tie-break via
// packed (float_bits, idx) uint64 min. Dists are always positive so float
// bit pattern ordering == value ordering.
// ---------------------------------------------------------------------------
__global__ void __launch_bounds__(256)
k_argmin(const float* __restrict__ z, const float* __restrict__ cb) {
    __shared__ float zs[BM][BD + 1];
    __shared__ float ws[BD][BK + 1];
    __shared__ unsigned long long red[BM][16];

    int tid = threadIdx.x;
    int tx = tid & 15;
    int ty = tid >> 4;
    int rowBase = blockIdx.x * BM;
    int kBase   = blockIdx.y * KSPAN;

    float c[4];
    unsigned long long best[4];
    #pragma unroll
    for (int i = 0; i < 4; i++) {
        c[i] = g_c[rowBase + ty * 4 + i];
        best[i] = ~0ULL;
    }

    for (int kt = 0; kt < KSPAN; kt += BK) {
        float acc[4][8];
        #pragma unroll
        for (int i = 0; i < 4; i++)
            #pragma unroll
            for (int j = 0; j < 8; j++)
                acc[i][j] = 0.0f;

        for (int dB = 0; dB < DDIM; dB += BD) {
            __syncthreads();
            // load z tile [64 x 16] : 256 float4, one per thread
            {
                int r  = tid >> 2;
                int d4 = (tid & 3) * 4;
                float4 v = *(const float4*)(z + (size_t)(rowBase + r) * DDIM + dB + d4);
                zs[r][d4 + 0] = v.x; zs[r][d4 + 1] = v.y;
                zs[r][d4 + 2] = v.z; zs[r][d4 + 3] = v.w;
            }
            // load codebook tile [128 x 16] -> transposed [16][128]
            #pragma unroll
            for (int t = 0; t < 2; t++) {
                int idx = tid + t * 256;
                int cde = idx >> 2;
                int d4  = (idx & 3) * 4;
                float4 v = *(const float4*)(cb + (size_t)(kBase + kt + cde) * DDIM + dB + d4);
                ws[d4 + 0][cde] = v.x; ws[d4 + 1][cde] = v.y;
                ws[d4 + 2][cde] = v.z; ws[d4 + 3][cde] = v.w;
            }
            __syncthreads();

            #pragma unroll
            for (int d = 0; d < BD; d++) {
                float rz[4], rw[8];
                #pragma unroll
                for (int i = 0; i < 4; i++) rz[i] = zs[ty * 4 + i][d];
                #pragma unroll
                for (int j = 0; j < 8; j++) rw[j] = ws[d][tx + 16 * j];
                #pragma unroll
                for (int i = 0; i < 4; i++)
                    #pragma unroll
                    for (int j = 0; j < 8; j++)
                        acc[i][j] = __fmaf_rn(rz[i], rw[j], acc[i][j]);
            }
        }

        // epilogue: quantize exactly like reference (single rounding of c-2*dot)
        #pragma unroll
        for (int i = 0; i < 4; i++) {
            #pragma unroll
            for (int j = 0; j < 8; j++) {
                float t = __fmaf_rn(-2.0f, acc[i][j], c[i]);
                unsigned long long p =
                    ((unsigned long long)__float_as_uint(t) << 32) |
                    (unsigned)(kBase + kt + tx + 16 * j);
                if (p < best[i]) best[i] = p;
            }
        }
    }

    // cross-thread reduction (16 tx-threads per row), then cross-block atomicMin
    __syncthreads();
    #pragma unroll
    for (int i = 0; i < 4; i++) red[ty * 4 + i][tx] = best[i];
    __syncthreads();
    if (tid < BM) {
        unsigned long long b = red[tid][0];
        #pragma unroll
        for (int x = 1; x < 16; x++) {
            unsigned long long v = red[tid][x];
            if (v < b) b = v;
        }
        atomicMin(&g_best[rowBase + tid], b);
    }
}

// ---------------------------------------------------------------------------
// Kernel 3: gather quantized vectors, emit straight-through output exactly as
// reference computes it elementwise: out = fl(z + fl(q - z)); accumulate
// fp32 (z-q)^2 (rounded like reference) into a double sum. Also writes indices.
// ---------------------------------------------------------------------------
__global__ void k_out(const float* __restrict__ z, const float* __restrict__ cb,
                      float* __restrict__ out) {
    __shared__ double sred[256];
    int n = blockIdx.x;
    int d = threadIdx.x;
    unsigned idx = (unsigned)(g_best[n] & 0xffffffffu);
    float zv = z[(size_t)n * DDIM + d];
    float qv = cb[(size_t)idx * DDIM + d];
    out[(size_t)n * DDIM + d] = zv + (qv - zv);   // straight-through, fp32 ops
    float diff = zv - qv;
    float sq = diff * diff;
    sred[d] = (double)sq;
    __syncthreads();
    #pragma unroll
    for (int o = 128; o > 0; o >>= 1) {
        if (d < o) sred[d] += sred[d + o];
        __syncthreads();
    }
    if (d == 0) {
        atomicAdd(&g_loss, sred[0]);
        out[(size_t)NROWS * DDIM + 1 + n] = (float)idx;
    }
}

// ---------------------------------------------------------------------------
// Kernel 4: finalize vq_loss = fl(m + fl(0.25*m)) with m = mean((z-q)^2)
// ---------------------------------------------------------------------------
__global__ void k_loss(float* __restrict__ out) {
    float m = (float)(g_loss / (double)((size_t)NROWS * DDIM));
    out[(size_t)NROWS * DDIM] = m + 0.25f * m;
}

// ---------------------------------------------------------------------------
extern "C" void kernel_launch(void* const* d_in, const int* in_sizes, int n_in,
                              void* d_out, int out_size) {
    const float* z  = (const float*)d_in[0];
    const float* cb = (const float*)d_in[1];
    // defensive: identify by size (z has 4194304 elems, codebook 2097152)
    if (n_in >= 2 && in_sizes[0] == KCODES * DDIM && in_sizes[1] == NROWS * DDIM) {
        z  = (const float*)d_in[1];
        cb = (const float*)d_in[0];
    }
    float* out = (float*)d_out;
    (void)out_size;

    k_init<<<NROWS / 8, 256>>>(z);
    dim3 g2(NROWS / BM, KCODES / KSPAN);
    k_argmin<<<g2, 256>>>(z, cb);
    k_out<<<NROWS, 256>>>(z, cb, out);
    k_loss<<<1, 1>>>(out);
}